// round 6
// baseline (speedup 1.0000x reference)
#include <cuda_runtime.h>
#include <math.h>

#define HW 4096
#define NC 256
#define NB 4
#define NBLK 148     // main kernel: one block per SM, all co-resident (wave-1)
#define NBLK_G 128   // gamma-path kernel

// ---- device scratch (16B-aligned: accessed via float4) ----
__device__ __align__(16) float g_ch_avg[NB*NC];
__device__ __align__(16) float g_ch_max[NB*NC];
__device__ __align__(16) float g_sp_avg[NB*HW];
__device__ __align__(16) float g_sp_max[NB*HW];
// attention scratch (only used when gamma != 0; never in this bench)
__device__ __align__(16) float g_q[NB*32*HW];
__device__ __align__(16) float g_k[NB*32*HW];
__device__ __align__(16) float g_v[NB*NC*HW];

// ---- software global barriers (generation counters only grow -> replay-safe) ----
__device__ unsigned g_barA_cnt = 0;
__device__ unsigned g_barA_gen = 0;
__device__ unsigned g_barB_cnt = 0;
__device__ unsigned g_barB_gen = 0;

__device__ __forceinline__ void gbarrier(unsigned* cnt, unsigned* gen, unsigned nb) {
    __syncthreads();
    if (threadIdx.x == 0) {
        unsigned g = *(volatile unsigned*)gen;
        __threadfence();
        unsigned a = atomicAdd(cnt, 1u);
        if (a == nb - 1u) {
            *(volatile unsigned*)cnt = 0u;
            __threadfence();
            atomicAdd(gen, 1u);            // release
        } else {
            while (*(volatile unsigned*)gen == g) { }
            __threadfence();               // acquire
        }
    }
    __syncthreads();
}

// ============ main path: one persistent kernel, 4 phases ============
__global__ void __launch_bounds__(256, 1) k_main(const float* __restrict__ x,
                       const float* __restrict__ w1, const float* __restrict__ w2,
                       const float* __restrict__ w_sp, float* __restrict__ out) {
    int t = threadIdx.x, blk = blockIdx.x;
    int lane = t & 31, wid = t >> 5;

    __shared__ float ws[8], wm[8];
    __shared__ float sa4[NB][256], sx4[NB][256], sh4[NB][16];
    __shared__ __align__(16) float att[NB][256];
    __shared__ float4 ssum[256], smx[256];
    __shared__ float cw[98], hsa[10][64], hsx[10][64];
    __shared__ __align__(16) float satt[256];

    // ---- phase 1: per-(b,c) spatial mean & max ----
    for (int pair = blk; pair < NB * NC; pair += NBLK) {
        const float4* xr = reinterpret_cast<const float4*>(x + (size_t)pair * HW);
        float s = 0.f, m = -1e30f;
#pragma unroll
        for (int i = 0; i < 4; i++) {
            float4 v = xr[t + i * 256];
            s += v.x + v.y + v.z + v.w;
            m = fmaxf(m, fmaxf(fmaxf(v.x, v.y), fmaxf(v.z, v.w)));
        }
#pragma unroll
        for (int o = 16; o > 0; o >>= 1) {
            s += __shfl_down_sync(0xffffffffu, s, o);
            m = fmaxf(m, __shfl_down_sync(0xffffffffu, m, o));
        }
        if (lane == 0) { ws[wid] = s; wm[wid] = m; }
        __syncthreads();
        if (t == 0) {
            float S = 0.f, M = -1e30f;
#pragma unroll
            for (int w = 0; w < 8; w++) { S += ws[w]; M = fmaxf(M, wm[w]); }
            g_ch_avg[pair] = S * (1.f / HW);
            g_ch_max[pair] = M;
        }
        __syncthreads();
    }
    gbarrier(&g_barA_cnt, &g_barA_gen, NBLK);

    // ---- phase 2: channel MLP, computed redundantly in every block ----
#pragma unroll
    for (int b = 0; b < NB; b++) {
        sa4[b][t] = g_ch_avg[b * 256 + t];
        sx4[b][t] = g_ch_max[b * 256 + t];
    }
    __syncthreads();
    if (t < 64) {               // thread = (b, hidden unit)
        int b = t >> 4, h = t & 15;
        const float* wr = w1 + h * 256;
        float ha = 0.f, hm = 0.f, ha2 = 0.f, hm2 = 0.f;
#pragma unroll 4
        for (int c = 0; c < 256; c += 2) {
            float w0 = wr[c], w1v = wr[c + 1];
            ha  += sa4[b][c] * w0;     hm  += sx4[b][c] * w0;
            ha2 += sa4[b][c + 1] * w1v; hm2 += sx4[b][c + 1] * w1v;
        }
        sh4[b][h] = fmaxf(ha + ha2, 0.f) + fmaxf(hm + hm2, 0.f);
    }
    __syncthreads();
    {
        const float* w2r = w2 + t * 16;
#pragma unroll
        for (int b = 0; b < NB; b++) {
            float o = 0.f;
#pragma unroll
            for (int r = 0; r < 16; r++) o += sh4[b][r] * w2r[r];
            att[b][t] = 1.f / (1.f + expf(-o));
        }
    }
    __syncthreads();

    // ---- phase 3: per-pixel channel mean & max of (x * att) ----
    // 256 tiles of 64 pixels; threads: pq = t&15 (4px quad), cgrp = t>>4 (16 ch)
    for (int it = blk; it < 256; it += NBLK) {
        int b = it >> 6;
        int pq = t & 15, cgrp = t >> 4;
        int p0 = (it & 63) * 64 + pq * 4;
        int c0 = cgrp * 16;
        const float* xb = x + ((size_t)b << 20) + p0;
        float4 s = {0.f, 0.f, 0.f, 0.f};
        float4 m = {-1e30f, -1e30f, -1e30f, -1e30f};
#pragma unroll
        for (int k = 0; k < 16; k++) {
            float a = att[b][c0 + k];
            float4 v = *reinterpret_cast<const float4*>(xb + ((size_t)(c0 + k) << 12));
            v.x *= a; v.y *= a; v.z *= a; v.w *= a;
            s.x += v.x; s.y += v.y; s.z += v.z; s.w += v.w;
            m.x = fmaxf(m.x, v.x); m.y = fmaxf(m.y, v.y);
            m.z = fmaxf(m.z, v.z); m.w = fmaxf(m.w, v.w);
        }
        ssum[t] = s; smx[t] = m; __syncthreads();
        if (t < 16) {
            float4 ts = {0.f, 0.f, 0.f, 0.f};
            float4 tm = {-1e30f, -1e30f, -1e30f, -1e30f};
#pragma unroll
            for (int g = 0; g < 16; g++) {
                float4 a = ssum[g * 16 + t], q = smx[g * 16 + t];
                ts.x += a.x; ts.y += a.y; ts.z += a.z; ts.w += a.w;
                tm.x = fmaxf(tm.x, q.x); tm.y = fmaxf(tm.y, q.y);
                tm.z = fmaxf(tm.z, q.z); tm.w = fmaxf(tm.w, q.w);
            }
            ts.x *= (1.f / 256.f); ts.y *= (1.f / 256.f);
            ts.z *= (1.f / 256.f); ts.w *= (1.f / 256.f);
            int p = (it & 63) * 64 + t * 4;
            *reinterpret_cast<float4*>(&g_sp_avg[(b << 12) + p]) = ts;
            *reinterpret_cast<float4*>(&g_sp_max[(b << 12) + p]) = tm;
        }
        __syncthreads();
    }
    gbarrier(&g_barA_cnt, &g_barA_gen, NBLK);

    // ---- phase 4: 7x7 conv (+sigmoid) and final apply ----
    if (t < 98) cw[t] = w_sp[t];
    __syncthreads();
    for (int it = blk; it < 256; it += NBLK) {
        int b = it >> 6, tile = (it >> 2) & 15, cg = it & 3;
        for (int i = t; i < 640; i += 256) {
            int r = i >> 6, cx = i & 63;
            int gy = tile * 4 + r - 3;
            float va = 0.f, vm = 0.f;
            if ((unsigned)gy < 64u) {
                va = g_sp_avg[b * 4096 + gy * 64 + cx];
                vm = g_sp_max[b * 4096 + gy * 64 + cx];
            }
            hsa[r][cx] = va; hsx[r][cx] = vm;
        }
        __syncthreads();
        {
            int r = t >> 6, cx = t & 63;
            float acc = 0.f;
#pragma unroll
            for (int ky = 0; ky < 7; ky++) {
#pragma unroll
                for (int kx = 0; kx < 7; kx++) {
                    int ix = cx + kx - 3;
                    if ((unsigned)ix < 64u) {
                        acc += cw[ky * 7 + kx] * hsa[r + ky][ix]
                             + cw[49 + ky * 7 + kx] * hsx[r + ky][ix];
                    }
                }
            }
            satt[t] = 1.f / (1.f + expf(-acc));
        }
        __syncthreads();
        const float* xb = x   + ((size_t)b << 20) + ((size_t)cg << 18) + tile * 256;
        float*       ob = out + ((size_t)b << 20) + ((size_t)cg << 18) + tile * 256;
#pragma unroll
        for (int k = 0; k < 16; k++) {
            int idx = k * 256 + t;
            int cl = idx >> 6, pquad = idx & 63;
            float a = att[b][cg * 64 + cl];
            float4 sv = *reinterpret_cast<const float4*>(&satt[pquad * 4]);
            float4 xv = *reinterpret_cast<const float4*>(xb + ((size_t)cl << 12) + pquad * 4);
            float4 o;
            o.x = xv.x * a * sv.x; o.y = xv.y * a * sv.y;
            o.z = xv.z * a * sv.z; o.w = xv.w * a * sv.w;
            *reinterpret_cast<float4*>(ob + ((size_t)cl << 12) + pquad * 4) = o;
        }
        __syncthreads();
    }
}

// ============ gamma != 0 path (exact; exits immediately when gamma == 0) ============
__global__ void __launch_bounds__(256, 1) k_nonlocal(float* __restrict__ out,
                           const float* __restrict__ wq, const float* __restrict__ bq,
                           const float* __restrict__ wk, const float* __restrict__ bk,
                           const float* __restrict__ wv, const float* __restrict__ bv,
                           const float* __restrict__ gamma) {
    float g = gamma[0];
    if (g == 0.f) return;
    int t = threadIdx.x;
    __shared__ __align__(16) float pool[256 * 32];   // xs (proj) / sbuf (attn)
    __shared__ float red[256], qv[32];

    // ---- phase A: q/k/v projections of out (x2) ----
    for (int wkid = blockIdx.x; wkid < 128 * NB; wkid += NBLK_G) {
        int chunk = wkid & 127, b = wkid >> 7;
        __syncthreads();
        {
            const float* src = out + ((size_t)(b * 256 + t)) * HW + chunk * 32;
            for (int p = 0; p < 32; p += 4) {
                float4 v = *reinterpret_cast<const float4*>(src + p);
                pool[t * 32 + p] = v.x; pool[t * 32 + p + 1] = v.y;
                pool[t * 32 + p + 2] = v.z; pool[t * 32 + p + 3] = v.w;
            }
        }
        __syncthreads();
        for (int k = 0; k < 40; k++) {        // 320 outputs * 32 px / 256 threads
            int oi = k * 256 + t;
            int o = oi >> 5, p = oi & 31;
            const float* wr; float bias; float* dst; int row;
            if (o < 32)      { wr = wq + o * 256;        bias = bq[o];      dst = g_q; row = b * 32 + o; }
            else if (o < 64) { int r = o - 32; wr = wk + r * 256; bias = bk[r]; dst = g_k; row = b * 32 + r; }
            else             { int r = o - 64; wr = wv + r * 256; bias = bv[r]; dst = g_v; row = b * 256 + r; }
            float acc = bias;
            for (int c = 0; c < 256; c++) acc += wr[c] * pool[c * 32 + p];
            dst[(size_t)row * HW + chunk * 32 + p] = acc;
        }
    }
    gbarrier(&g_barB_cnt, &g_barB_gen, NBLK_G);

    // ---- phase B: per (b, query i) softmax attention ----
    for (int bi = blockIdx.x; bi < NB * HW; bi += NBLK_G) {
        int b = bi >> 12, i = bi & 4095;
        if (t < 32) qv[t] = g_q[(b * 32 + t) * HW + i];
        __syncthreads();
        float lm = -1e30f;
        for (int j = t; j < 4096; j += 256) {
            float s = 0.f;
#pragma unroll
            for (int d = 0; d < 32; d++) s += qv[d] * g_k[(b * 32 + d) * HW + j];
            pool[j] = s; lm = fmaxf(lm, s);
        }
        red[t] = lm; __syncthreads();
        for (int o = 128; o > 0; o >>= 1) {
            if (t < o) red[t] = fmaxf(red[t], red[t + o]);
            __syncthreads();
        }
        float m = red[0]; __syncthreads();
        float ls = 0.f;
        for (int j = t; j < 4096; j += 256) {
            float e = expf(pool[j] - m);
            pool[j] = e; ls += e;
        }
        red[t] = ls; __syncthreads();
        for (int o = 128; o > 0; o >>= 1) {
            if (t < o) red[t] += red[t + o];
            __syncthreads();
        }
        float inv = 1.f / red[0]; __syncthreads();
        float acc = 0.f;
        const float* vr = g_v + (size_t)(b * 256 + t) * HW;
        for (int j = 0; j < 4096; j++) acc += vr[j] * pool[j];
        out[(b * 256 + t) * HW + i] += g * acc * inv;
        __syncthreads();
    }
}

extern "C" void kernel_launch(void* const* d_in, const int* in_sizes, int n_in,
                              void* d_out, int out_size) {
    const float* x     = (const float*)d_in[0];
    const float* w1    = (const float*)d_in[1];
    const float* w2    = (const float*)d_in[2];
    const float* w_sp  = (const float*)d_in[3];
    const float* wq    = (const float*)d_in[4];
    const float* bq    = (const float*)d_in[5];
    const float* wk    = (const float*)d_in[6];
    const float* bk    = (const float*)d_in[7];
    const float* wv    = (const float*)d_in[8];
    const float* bv    = (const float*)d_in[9];
    const float* gamma = (const float*)d_in[10];
    float* out = (float*)d_out;

    k_main<<<NBLK, 256>>>(x, w1, w2, w_sp, out);
    k_nonlocal<<<NBLK_G, 256>>>(out, wq, bq, wk, bk, wv, bv, gamma);
}

// round 8
// speedup vs baseline: 1.3819x; 1.3819x over previous
#include <cuda_runtime.h>
#include <math.h>

#define HW 4096
#define NC 256
#define NB 4
#define NBLK_G 128   // gamma-path kernel (all co-resident; safe for its internal barrier)

// ---- device scratch (16B-aligned: accessed via float4) ----
__device__ __align__(16) float g_ch_avg[NB*NC];
__device__ __align__(16) float g_ch_max[NB*NC];
// attention scratch (only used when gamma != 0; never in this bench)
__device__ __align__(16) float g_q[NB*32*HW];
__device__ __align__(16) float g_k[NB*32*HW];
__device__ __align__(16) float g_v[NB*NC*HW];
__device__ unsigned g_barB_cnt = 0;
__device__ unsigned g_barB_gen = 0;

__device__ __forceinline__ void gbarrier(unsigned* cnt, unsigned* gen, unsigned nb) {
    __syncthreads();
    if (threadIdx.x == 0) {
        unsigned g = *(volatile unsigned*)gen;
        __threadfence();
        unsigned a = atomicAdd(cnt, 1u);
        if (a == nb - 1u) {
            *(volatile unsigned*)cnt = 0u;
            __threadfence();
            atomicAdd(gen, 1u);
        } else {
            while (*(volatile unsigned*)gen == g) { }
            __threadfence();
        }
    }
    __syncthreads();
}

// K1: per-(b,c) spatial mean & max over 4096 pixels (1024 blocks; DRAM pass)
__global__ void k_chstats(const float* __restrict__ x) {
    int bc = blockIdx.x;
    int t  = threadIdx.x;           // 256
    const float4* xr = reinterpret_cast<const float4*>(x + (size_t)bc * HW);
    float s = 0.f, m = -1e30f;
#pragma unroll
    for (int i = 0; i < 4; i++) {
        float4 v = xr[t + i * 256];
        s += v.x + v.y + v.z + v.w;
        m = fmaxf(m, fmaxf(fmaxf(v.x, v.y), fmaxf(v.z, v.w)));
    }
    __shared__ float ss[256], sm[256];
    ss[t] = s; sm[t] = m; __syncthreads();
    for (int o = 128; o > 0; o >>= 1) {
        if (t < o) { ss[t] += ss[t + o]; sm[t] = fmaxf(sm[t], sm[t + o]); }
        __syncthreads();
    }
    if (t == 0) { g_ch_avg[bc] = ss[0] * (1.f / HW); g_ch_max[bc] = sm[0]; }
}

// K2: fully fused — inline channel-MLP, halo-recomputed per-pixel stats,
// 7x7 conv + sigmoid, final apply. Grid (4, 16), 640 threads (20 warps).
// Block handles a 4-row output tile; recomputes stats for its 10-row halo.
__global__ void __launch_bounds__(640) k_fused(
        const float* __restrict__ x,
        const float* __restrict__ w1, const float* __restrict__ w2,
        const float* __restrict__ w_sp, float* __restrict__ out) {
    int b = blockIdx.x, tile = blockIdx.y;
    int t = threadIdx.x;
    __shared__ float sa_[256], sx_[256], sh[16], cw[98];
    __shared__ __align__(16) float att[256];
    __shared__ float4 ssum4[640], smx4[640];
    __shared__ __align__(16) float stat_avg[640], stat_max[640];
    __shared__ __align__(16) float satt[256];

    // ---- phase A: channel MLP (redundant per block; 16 warps, one hidden unit each) ----
    if (t < 256) { sa_[t] = g_ch_avg[b * 256 + t]; sx_[t] = g_ch_max[b * 256 + t]; }
    if (t >= 512 && t < 610) cw[t - 512] = w_sp[t - 512];
    __syncthreads();
    if (t < 512) {
        int h = t >> 5, lid = t & 31;
        const float* wr = w1 + h * 256;
        float ha = 0.f, hm = 0.f;
#pragma unroll
        for (int k = 0; k < 8; k++) {
            int c = k * 32 + lid;
            float wv = wr[c];
            ha += sa_[c] * wv; hm += sx_[c] * wv;
        }
#pragma unroll
        for (int o = 16; o > 0; o >>= 1) {
            ha += __shfl_down_sync(0xffffffffu, ha, o);
            hm += __shfl_down_sync(0xffffffffu, hm, o);
        }
        if (lid == 0) sh[h] = fmaxf(ha, 0.f) + fmaxf(hm, 0.f);
    }
    __syncthreads();
    if (t < 256) {
        float o = 0.f;
        const float* w2r = w2 + t * 16;
#pragma unroll
        for (int r = 0; r < 16; r++) o += sh[r] * w2r[r];
        att[t] = 1.f / (1.f + expf(-o));
    }
    __syncthreads();

    // ---- phase B: per-pixel channel mean/max of x*att over the 10-row halo ----
    // 160 pixel-quads (10 rows x 16 quads) x 4 channel-groups of 64.
    {
        int quad = t % 160, cg = t / 160;       // 160 = 5 warps -> warp-aligned split
        int r = quad >> 4, qx = quad & 15;
        int gy = tile * 4 + r - 3;
        float4 s = {0.f, 0.f, 0.f, 0.f};
        float4 m = {-1e30f, -1e30f, -1e30f, -1e30f};
        if ((unsigned)gy < 64u) {
            const float* base = x + ((size_t)b << 20) + gy * 64 + qx * 4;
            int c0 = cg * 64;
#pragma unroll 8
            for (int k = 0; k < 64; k++) {
                float a = att[c0 + k];
                float4 v = *reinterpret_cast<const float4*>(base + ((size_t)(c0 + k) << 12));
                v.x *= a; v.y *= a; v.z *= a; v.w *= a;
                s.x += v.x; s.y += v.y; s.z += v.z; s.w += v.w;
                m.x = fmaxf(m.x, v.x); m.y = fmaxf(m.y, v.y);
                m.z = fmaxf(m.z, v.z); m.w = fmaxf(m.w, v.w);
            }
        }
        ssum4[t] = s; smx4[t] = m;
    }
    __syncthreads();
    if (t < 160) {
        int r = t >> 4;
        int gy = tile * 4 + r - 3;
        float4 ts = {0.f, 0.f, 0.f, 0.f}, tm = {0.f, 0.f, 0.f, 0.f};
        if ((unsigned)gy < 64u) {
            float4 a0 = ssum4[t], a1 = ssum4[t + 160], a2 = ssum4[t + 320], a3 = ssum4[t + 480];
            float4 m0 = smx4[t],  m1 = smx4[t + 160],  m2 = smx4[t + 320],  m3 = smx4[t + 480];
            ts.x = (a0.x + a1.x + a2.x + a3.x) * (1.f / 256.f);
            ts.y = (a0.y + a1.y + a2.y + a3.y) * (1.f / 256.f);
            ts.z = (a0.z + a1.z + a2.z + a3.z) * (1.f / 256.f);
            ts.w = (a0.w + a1.w + a2.w + a3.w) * (1.f / 256.f);
            tm.x = fmaxf(fmaxf(m0.x, m1.x), fmaxf(m2.x, m3.x));
            tm.y = fmaxf(fmaxf(m0.y, m1.y), fmaxf(m2.y, m3.y));
            tm.z = fmaxf(fmaxf(m0.z, m1.z), fmaxf(m2.z, m3.z));
            tm.w = fmaxf(fmaxf(m0.w, m1.w), fmaxf(m2.w, m3.w));
        }
        *reinterpret_cast<float4*>(&stat_avg[t * 4]) = ts;
        *reinterpret_cast<float4*>(&stat_max[t * 4]) = tm;
    }
    __syncthreads();

    // ---- phase C: 7x7 conv + sigmoid (256 output pixels) ----
    if (t < 256) {
        int r = t >> 6, cx = t & 63;
        float acc = 0.f;
#pragma unroll
        for (int ky = 0; ky < 7; ky++) {
#pragma unroll
            for (int kx = 0; kx < 7; kx++) {
                int ix = cx + kx - 3;
                if ((unsigned)ix < 64u) {
                    acc += cw[ky * 7 + kx] * stat_avg[(r + ky) * 64 + ix]
                         + cw[49 + ky * 7 + kx] * stat_max[(r + ky) * 64 + ix];
                }
            }
        }
        satt[t] = 1.f / (1.f + expf(-acc));
    }
    __syncthreads();

    // ---- phase D: apply over 256 channels x 256 pixels ----
    const float* xb = x   + ((size_t)b << 20) + tile * 256;
    float*       ob = out + ((size_t)b << 20) + tile * 256;
    for (int i = t; i < 16384; i += 640) {       // 16384 quads = 256 ch x 64 quads
        int c = i >> 6, q = i & 63;
        float a = att[c];
        float4 sv = *reinterpret_cast<const float4*>(&satt[q * 4]);
        float4 xv = *reinterpret_cast<const float4*>(xb + ((size_t)c << 12) + q * 4);
        float4 o;
        o.x = xv.x * a * sv.x; o.y = xv.y * a * sv.y;
        o.z = xv.z * a * sv.z; o.w = xv.w * a * sv.w;
        *reinterpret_cast<float4*>(ob + ((size_t)c << 12) + q * 4) = o;
    }
}

// ============ gamma != 0 path (exact; exits immediately when gamma == 0) ============
__global__ void __launch_bounds__(256, 1) k_nonlocal(float* __restrict__ out,
                           const float* __restrict__ wq, const float* __restrict__ bq,
                           const float* __restrict__ wk, const float* __restrict__ bk,
                           const float* __restrict__ wv, const float* __restrict__ bv,
                           const float* __restrict__ gamma) {
    float g = gamma[0];
    if (g == 0.f) return;
    int t = threadIdx.x;
    __shared__ __align__(16) float pool[256 * 32];
    __shared__ float red[256], qv[32];

    // phase A: q/k/v projections of out (x2)
    for (int wkid = blockIdx.x; wkid < 128 * NB; wkid += NBLK_G) {
        int chunk = wkid & 127, b = wkid >> 7;
        __syncthreads();
        {
            const float* src = out + ((size_t)(b * 256 + t)) * HW + chunk * 32;
            for (int p = 0; p < 32; p += 4) {
                float4 v = *reinterpret_cast<const float4*>(src + p);
                pool[t * 32 + p] = v.x; pool[t * 32 + p + 1] = v.y;
                pool[t * 32 + p + 2] = v.z; pool[t * 32 + p + 3] = v.w;
            }
        }
        __syncthreads();
        for (int k = 0; k < 40; k++) {
            int oi = k * 256 + t;
            int o = oi >> 5, p = oi & 31;
            const float* wr; float bias; float* dst; int row;
            if (o < 32)      { wr = wq + o * 256;        bias = bq[o];      dst = g_q; row = b * 32 + o; }
            else if (o < 64) { int r = o - 32; wr = wk + r * 256; bias = bk[r]; dst = g_k; row = b * 32 + r; }
            else             { int r = o - 64; wr = wv + r * 256; bias = bv[r]; dst = g_v; row = b * 256 + r; }
            float acc = bias;
            for (int c = 0; c < 256; c++) acc += wr[c] * pool[c * 32 + p];
            dst[(size_t)row * HW + chunk * 32 + p] = acc;
        }
    }
    gbarrier(&g_barB_cnt, &g_barB_gen, NBLK_G);

    // phase B: per (b, query i) softmax attention
    for (int bi = blockIdx.x; bi < NB * HW; bi += NBLK_G) {
        int b = bi >> 12, i = bi & 4095;
        if (t < 32) qv[t] = g_q[(b * 32 + t) * HW + i];
        __syncthreads();
        float lm = -1e30f;
        for (int j = t; j < 4096; j += 256) {
            float s = 0.f;
#pragma unroll
            for (int d = 0; d < 32; d++) s += qv[d] * g_k[(b * 32 + d) * HW + j];
            pool[j] = s; lm = fmaxf(lm, s);
        }
        red[t] = lm; __syncthreads();
        for (int o = 128; o > 0; o >>= 1) {
            if (t < o) red[t] = fmaxf(red[t], red[t + o]);
            __syncthreads();
        }
        float m = red[0]; __syncthreads();
        float ls = 0.f;
        for (int j = t; j < 4096; j += 256) {
            float e = expf(pool[j] - m);
            pool[j] = e; ls += e;
        }
        red[t] = ls; __syncthreads();
        for (int o = 128; o > 0; o >>= 1) {
            if (t < o) red[t] += red[t + o];
            __syncthreads();
        }
        float inv = 1.f / red[0]; __syncthreads();
        float acc = 0.f;
        const float* vr = g_v + (size_t)(b * 256 + t) * HW;
        for (int j = 0; j < 4096; j++) acc += vr[j] * pool[j];
        out[(b * 256 + t) * HW + i] += g * acc * inv;
        __syncthreads();
    }
}

extern "C" void kernel_launch(void* const* d_in, const int* in_sizes, int n_in,
                              void* d_out, int out_size) {
    const float* x     = (const float*)d_in[0];
    const float* w1    = (const float*)d_in[1];
    const float* w2    = (const float*)d_in[2];
    const float* w_sp  = (const float*)d_in[3];
    const float* wq    = (const float*)d_in[4];
    const float* bq    = (const float*)d_in[5];
    const float* wk    = (const float*)d_in[6];
    const float* bk    = (const float*)d_in[7];
    const float* wv    = (const float*)d_in[8];
    const float* bv    = (const float*)d_in[9];
    const float* gamma = (const float*)d_in[10];
    float* out = (float*)d_out;

    k_chstats<<<NB * NC, 256>>>(x);
    k_fused<<<dim3(NB, 16), 640>>>(x, w1, w2, w_sp, out);
    k_nonlocal<<<NBLK_G, 256>>>(out, wq, bq, wk, bk, wv, bv, gamma);
}

// round 9
// speedup vs baseline: 1.8277x; 1.3226x over previous
#include <cuda_runtime.h>
#include <math.h>

#define HW 4096
#define NC 256
#define NB 4
#define NBG 256      // convapply grid (wave-1 co-resident at 2 blocks/SM)

// ---- device scratch (16B-aligned: accessed via float4) ----
__device__ __align__(16) float g_ch_avg[NB*NC];
__device__ __align__(16) float g_ch_max[NB*NC];
__device__ __align__(16) float g_ch_att[NB*NC];
__device__ __align__(16) float g_sp_avg[NB*HW];
__device__ __align__(16) float g_sp_max[NB*HW];
// attention scratch (only used when gamma != 0; never in this bench)
__device__ __align__(16) float g_q[NB*32*HW];
__device__ __align__(16) float g_k[NB*32*HW];
__device__ __align__(16) float g_v[NB*NC*HW];
__device__ unsigned g_bar_cnt = 0;
__device__ unsigned g_bar_gen = 0;

__device__ __forceinline__ void gbarrier(unsigned* cnt, unsigned* gen, unsigned nb) {
    __syncthreads();
    if (threadIdx.x == 0) {
        unsigned g = *(volatile unsigned*)gen;
        __threadfence();
        unsigned a = atomicAdd(cnt, 1u);
        if (a == nb - 1u) {
            *(volatile unsigned*)cnt = 0u;
            __threadfence();
            atomicAdd(gen, 1u);
        } else {
            while (*(volatile unsigned*)gen == g) { }
            __threadfence();
        }
    }
    __syncthreads();
}

// K1: per-(b,c) spatial mean & max. 512 blocks x 256 thr; 2 rows per block;
// 8 independent float4 loads per thread (MLP_p1=8); warp-shuffle reduce.
__global__ void k_chstats(const float* __restrict__ x) {
    int t = threadIdx.x, lane = t & 31, wid = t >> 5;
    int bc = blockIdx.x * 2 + (t >> 7);
    int i  = t & 127;
    const float4* xr = reinterpret_cast<const float4*>(x + (size_t)bc * HW);
    float s = 0.f, m = -1e30f;
#pragma unroll
    for (int j = 0; j < 8; j++) {
        float4 v = xr[i + j * 128];
        s += v.x + v.y + v.z + v.w;
        m = fmaxf(m, fmaxf(fmaxf(v.x, v.y), fmaxf(v.z, v.w)));
    }
#pragma unroll
    for (int o = 16; o > 0; o >>= 1) {
        s += __shfl_down_sync(0xffffffffu, s, o);
        m = fmaxf(m, __shfl_down_sync(0xffffffffu, m, o));
    }
    __shared__ float ws[8], wm[8];
    if (lane == 0) { ws[wid] = s; wm[wid] = m; }
    __syncthreads();
    if (t < 2) {
        int base = t * 4;
        float S = ws[base] + ws[base + 1] + ws[base + 2] + ws[base + 3];
        float M = fmaxf(fmaxf(wm[base], wm[base + 1]), fmaxf(wm[base + 2], wm[base + 3]));
        g_ch_avg[blockIdx.x * 2 + t] = S * (1.f / HW);
        g_ch_max[blockIdx.x * 2 + t] = M;
    }
}

// K2: inline channel-MLP (redundant per block) + per-pixel channel mean/max
// of (x * ch_att). 256 blocks: b = blk>>6, 64 pixels per block.
__global__ void k_spstats(const float* __restrict__ x,
                          const float* __restrict__ w1, const float* __restrict__ w2) {
    int t   = threadIdx.x;
    int blk = blockIdx.x;
    int b   = blk >> 6;
    __shared__ float sa_[256], sx_[256], sh[16];
    __shared__ __align__(16) float att[256];
    __shared__ float4 ssum[256], smx[256];

    sa_[t] = g_ch_avg[b * 256 + t];
    sx_[t] = g_ch_max[b * 256 + t];
    __syncthreads();
    {
        int wid = t >> 5, lid = t & 31;
#pragma unroll
        for (int u = 0; u < 2; u++) {
            int h = wid * 2 + u;
            const float* wr = w1 + h * 256;
            float ha = 0.f, hm = 0.f;
#pragma unroll
            for (int k = 0; k < 8; k++) {
                int c = k * 32 + lid;
                float wv = wr[c];
                ha += sa_[c] * wv; hm += sx_[c] * wv;
            }
#pragma unroll
            for (int o = 16; o > 0; o >>= 1) {
                ha += __shfl_down_sync(0xffffffffu, ha, o);
                hm += __shfl_down_sync(0xffffffffu, hm, o);
            }
            if (lid == 0) sh[h] = fmaxf(ha, 0.f) + fmaxf(hm, 0.f);
        }
    }
    __syncthreads();
    {
        float o = 0.f;
        const float* w2r = w2 + t * 16;
#pragma unroll
        for (int r = 0; r < 16; r++) o += sh[r] * w2r[r];
        att[t] = 1.f / (1.f + expf(-o));
        if ((blk & 63) == 0) g_ch_att[b * 256 + t] = att[t];
    }
    __syncthreads();

    int pq = t & 15, cgrp = t >> 4;
    int p0 = (blk & 63) * 64 + pq * 4;
    int c0 = cgrp * 16;
    const float* xb = x + ((size_t)b << 20) + p0;
    float4 s = {0.f, 0.f, 0.f, 0.f};
    float4 m = {-1e30f, -1e30f, -1e30f, -1e30f};
#pragma unroll
    for (int k = 0; k < 16; k++) {
        float a = att[c0 + k];
        float4 v = *reinterpret_cast<const float4*>(xb + ((size_t)(c0 + k) << 12));
        v.x *= a; v.y *= a; v.z *= a; v.w *= a;
        s.x += v.x; s.y += v.y; s.z += v.z; s.w += v.w;
        m.x = fmaxf(m.x, v.x); m.y = fmaxf(m.y, v.y);
        m.z = fmaxf(m.z, v.z); m.w = fmaxf(m.w, v.w);
    }
    ssum[t] = s; smx[t] = m; __syncthreads();
    if (t < 16) {
        float4 ts = {0.f, 0.f, 0.f, 0.f};
        float4 tm = {-1e30f, -1e30f, -1e30f, -1e30f};
#pragma unroll
        for (int g = 0; g < 16; g++) {
            float4 a = ssum[g * 16 + t], q = smx[g * 16 + t];
            ts.x += a.x; ts.y += a.y; ts.z += a.z; ts.w += a.w;
            tm.x = fmaxf(tm.x, q.x); tm.y = fmaxf(tm.y, q.y);
            tm.z = fmaxf(tm.z, q.z); tm.w = fmaxf(tm.w, q.w);
        }
        ts.x *= (1.f / 256.f); ts.y *= (1.f / 256.f);
        ts.z *= (1.f / 256.f); ts.w *= (1.f / 256.f);
        int p = (blk & 63) * 64 + t * 4;
        *reinterpret_cast<float4*>(&g_sp_avg[(b << 12) + p]) = ts;
        *reinterpret_cast<float4*>(&g_sp_max[(b << 12) + p]) = tm;
    }
}

// K3: fused 7x7 conv (+sigmoid) + final apply, then (gamma!=0 only) the full
// non-local attention with an internal grid barrier (grid=256 is wave-1
// co-resident at 2 blocks/SM, so the barrier is deadlock-free).
__global__ void __launch_bounds__(256, 2) k_convapply(
        const float* __restrict__ x, const float* __restrict__ w_sp,
        float* __restrict__ out,
        const float* __restrict__ wq, const float* __restrict__ bq,
        const float* __restrict__ wk, const float* __restrict__ bk,
        const float* __restrict__ wv, const float* __restrict__ bv,
        const float* __restrict__ gamma) {
    int b = blockIdx.x, tile = blockIdx.y, cg = blockIdx.z;
    int t = threadIdx.x;
    __shared__ __align__(16) float satt[256];
    __shared__ float w[98], sa[10][64], sx[10][64], catt[64];
    __shared__ __align__(16) float pool[8192];   // gamma path: xs / sbuf
    __shared__ float red[256], qv[32];

    if (t < 98) w[t] = w_sp[t];
    if (t >= 128 && t < 192) catt[t - 128] = g_ch_att[b * 256 + cg * 64 + (t - 128)];
    for (int i = t; i < 640; i += 256) {
        int r = i >> 6, cx = i & 63;
        int gy = tile * 4 + r - 3;
        float va = 0.f, vm = 0.f;
        if ((unsigned)gy < 64u) {
            va = g_sp_avg[b * 4096 + gy * 64 + cx];
            vm = g_sp_max[b * 4096 + gy * 64 + cx];
        }
        sa[r][cx] = va; sx[r][cx] = vm;
    }
    __syncthreads();
    {
        int r = t >> 6, cx = t & 63;
        float acc = 0.f;
#pragma unroll
        for (int ky = 0; ky < 7; ky++) {
#pragma unroll
            for (int kx = 0; kx < 7; kx++) {
                int ix = cx + kx - 3;
                if ((unsigned)ix < 64u) {
                    acc += w[ky * 7 + kx] * sa[r + ky][ix]
                         + w[49 + ky * 7 + kx] * sx[r + ky][ix];
                }
            }
        }
        satt[t] = 1.f / (1.f + expf(-acc));
    }
    __syncthreads();
    {
        const float* xb = x   + ((size_t)b << 20) + ((size_t)cg << 18) + tile * 256;
        float*       ob = out + ((size_t)b << 20) + ((size_t)cg << 18) + tile * 256;
#pragma unroll
        for (int k = 0; k < 16; k++) {
            int idx = k * 256 + t;
            int cl = idx >> 6, pquad = idx & 63;
            float a = catt[cl];
            float4 sv = *reinterpret_cast<const float4*>(&satt[pquad * 4]);
            float4 xv = *reinterpret_cast<const float4*>(xb + ((size_t)cl << 12) + pquad * 4);
            float4 o;
            o.x = xv.x * a * sv.x; o.y = xv.y * a * sv.y;
            o.z = xv.z * a * sv.z; o.w = xv.w * a * sv.w;
            *reinterpret_cast<float4*>(ob + ((size_t)cl << 12) + pquad * 4) = o;
        }
    }

    // ---- gamma != 0 path (exact; skipped entirely when gamma == 0) ----
    float g = gamma[0];
    if (g == 0.f) return;
    int bid = blockIdx.x + NB * (blockIdx.y + 16 * blockIdx.z);   // 0..255

    gbarrier(&g_bar_cnt, &g_bar_gen, NBG);   // out fully written

    // phase A: q/k/v projections of out (x2)
    for (int wkid = bid; wkid < 128 * NB; wkid += NBG) {
        int chunk = wkid & 127, bb = wkid >> 7;
        __syncthreads();
        {
            const float* src = out + ((size_t)(bb * 256 + t)) * HW + chunk * 32;
            for (int p = 0; p < 32; p += 4) {
                float4 v = *reinterpret_cast<const float4*>(src + p);
                pool[t * 32 + p] = v.x; pool[t * 32 + p + 1] = v.y;
                pool[t * 32 + p + 2] = v.z; pool[t * 32 + p + 3] = v.w;
            }
        }
        __syncthreads();
        for (int k = 0; k < 40; k++) {
            int oi = k * 256 + t;
            int o = oi >> 5, p = oi & 31;
            const float* wr; float bias; float* dst; int row;
            if (o < 32)      { wr = wq + o * 256;        bias = bq[o];      dst = g_q; row = bb * 32 + o; }
            else if (o < 64) { int r = o - 32; wr = wk + r * 256; bias = bk[r]; dst = g_k; row = bb * 32 + r; }
            else             { int r = o - 64; wr = wv + r * 256; bias = bv[r]; dst = g_v; row = bb * 256 + r; }
            float acc = bias;
            for (int c = 0; c < 256; c++) acc += wr[c] * pool[c * 32 + p];
            dst[(size_t)row * HW + chunk * 32 + p] = acc;
        }
    }
    gbarrier(&g_bar_cnt, &g_bar_gen, NBG);

    // phase B: per (b, query i) softmax attention
    for (int bi = bid; bi < NB * HW; bi += NBG) {
        int bb = bi >> 12, i = bi & 4095;
        if (t < 32) qv[t] = g_q[(bb * 32 + t) * HW + i];
        __syncthreads();
        float lm = -1e30f;
        for (int j = t; j < 4096; j += 256) {
            float s = 0.f;
#pragma unroll
            for (int d = 0; d < 32; d++) s += qv[d] * g_k[(bb * 32 + d) * HW + j];
            pool[j] = s; lm = fmaxf(lm, s);
        }
        red[t] = lm; __syncthreads();
        for (int o = 128; o > 0; o >>= 1) {
            if (t < o) red[t] = fmaxf(red[t], red[t + o]);
            __syncthreads();
        }
        float m = red[0]; __syncthreads();
        float ls = 0.f;
        for (int j = t; j < 4096; j += 256) {
            float e = expf(pool[j] - m);
            pool[j] = e; ls += e;
        }
        red[t] = ls; __syncthreads();
        for (int o = 128; o > 0; o >>= 1) {
            if (t < o) red[t] += red[t + o];
            __syncthreads();
        }
        float inv = 1.f / red[0]; __syncthreads();
        float acc = 0.f;
        const float* vr = g_v + (size_t)(bb * 256 + t) * HW;
        for (int j = 0; j < 4096; j++) acc += vr[j] * pool[j];
        out[(bb * 256 + t) * HW + i] += g * acc * inv;
        __syncthreads();
    }
}

extern "C" void kernel_launch(void* const* d_in, const int* in_sizes, int n_in,
                              void* d_out, int out_size) {
    const float* x     = (const float*)d_in[0];
    const float* w1    = (const float*)d_in[1];
    const float* w2    = (const float*)d_in[2];
    const float* w_sp  = (const float*)d_in[3];
    const float* wq    = (const float*)d_in[4];
    const float* bq    = (const float*)d_in[5];
    const float* wk    = (const float*)d_in[6];
    const float* bk    = (const float*)d_in[7];
    const float* wv    = (const float*)d_in[8];
    const float* bv    = (const float*)d_in[9];
    const float* gamma = (const float*)d_in[10];
    float* out = (float*)d_out;

    k_chstats<<<512, 256>>>(x);
    k_spstats<<<256, 256>>>(x, w1, w2);
    k_convapply<<<dim3(NB, 16, 4), 256>>>(x, w_sp, out, wq, bq, wk, bk, wv, bv, gamma);
}